// round 17
// baseline (speedup 1.0000x reference)
#include <cuda_runtime.h>
#include <cuda_bf16.h>
#include <math.h>
#include <stdint.h>

// ---------------- problem constants ----------------
#define DIM   4096
#define NH    32
#define NKV   8
#define HD    128
#define B_    2
#define S_    2048
#define M_    (B_*S_)          // 4096 rows

// ---------------- scratch (static device globals; no allocs allowed) -------
__device__ float g_q[(size_t)M_ * DIM];          // 64 MB
__device__ float g_k[(size_t)M_ * NKV * HD];     // 16 MB
__device__ float g_v[(size_t)M_ * NKV * HD];     // 16 MB
__device__ float g_att[(size_t)M_ * DIM];        // 64 MB

// ---------------- bf16 helpers ----------------------------------------------
// split f0,f1 (consecutive k) into packed bf16x2 hi and mid parts.
// pack convention: low half = f0 (even k), high half = f1 (odd k).
__device__ __forceinline__ void split_pack_bf16(float f0, float f1,
                                                uint32_t& h, uint32_t& m) {
    uint32_t hp;
    asm("cvt.rn.bf16x2.f32 %0, %1, %2;" : "=r"(hp) : "f"(f1), "f"(f0));
    const float h0 = __uint_as_float(hp << 16);
    const float h1 = __uint_as_float(hp & 0xffff0000u);
    const float r0 = f0 - h0;
    const float r1 = f1 - h1;
    asm("cvt.rn.bf16x2.f32 %0, %1, %2;" : "=r"(m) : "f"(r1), "f"(r0));
    h = hp;
}

__device__ __forceinline__ void mma_bf16(float c[4], uint32_t a0, uint32_t a1,
                                         uint32_t a2, uint32_t a3,
                                         uint32_t b0, uint32_t b1) {
    asm volatile(
        "mma.sync.aligned.m16n8k16.row.col.f32.bf16.bf16.f32 "
        "{%0,%1,%2,%3}, {%4,%5,%6,%7}, {%8,%9}, {%0,%1,%2,%3};"
        : "+f"(c[0]), "+f"(c[1]), "+f"(c[2]), "+f"(c[3])
        : "r"(a0), "r"(a1), "r"(a2), "r"(a3), "r"(b0), "r"(b1));
}

// =====================================================================
// BF16x3 tensor-core GEMM (hi*hi + hi*mid + mid*hi), fp32 accumulate.
// C[M,N] = A[M,K] @ B[K,N], all row-major.
// CTA tile 128x128x32, 8 warps (2x4), warp tile 64x32.
// smem: uint2-interleaved {hi, mid} per k-pair (one LDS.64 per fragment
// register pair — halves LDS wavefronts vs separate hi/mid planes).
//   A2 [128 rows][16 kpairs]  stride A2ST=20  (uint2 units, ≡4 mod 16)
//   B2 [16 kpairs][128 n]     stride B2ST=132 (uint2 units, ≡4 mod 16)
// =====================================================================
#define GBM 128
#define GBN 128
#define GBK 32
#define A2ST 20
#define B2ST 132
#define GEMM_SMEM ((GBM * A2ST + (GBK/2) * B2ST) * 8)   // 37376 B

__global__ __launch_bounds__(256, 1) void bf16_gemm_kernel(
    const float* __restrict__ A, const float* __restrict__ B,
    float* __restrict__ C, int M, int N, int K)
{
    extern __shared__ uint2 smg[];
    uint2* A2 = smg;
    uint2* B2 = smg + GBM * A2ST;

    const int tid  = threadIdx.x;
    const int wid  = tid >> 5;
    const int lane = tid & 31;
    const int wm   = wid >> 2;
    const int wn   = wid & 3;
    const int gid  = lane >> 2;
    const int tig  = lane & 3;

    const int by = blockIdx.y * GBM;
    const int bx = blockIdx.x * GBN;

    const int aR  = tid >> 3;          // 0..31 (+32 per iter)
    const int aC  = (tid & 7) * 4;     // k offset 0..28
    const int aKP = aC >> 1;           // kpair offset (0,2,...,14)
    const int bKP = tid >> 5;          // 0..7
    const int bC  = (tid & 31) * 4;    // n offset 0..124

    float acc[4][4][4];
#pragma unroll
    for (int i = 0; i < 4; i++)
#pragma unroll
        for (int j = 0; j < 4; j++)
#pragma unroll
            for (int t = 0; t < 4; t++) acc[i][j][t] = 0.f;

    const int nk = K / GBK;
    float4 pa[4];
    float4 pb[2][2];

#pragma unroll
    for (int it = 0; it < 4; it++)
        pa[it] = *(const float4*)(A + (size_t)(by + aR + it * 32) * K + aC);
#pragma unroll
    for (int it = 0; it < 2; it++) {
        const int kr = 2 * (bKP + it * 8);
        pb[it][0] = *(const float4*)(B + (size_t)kr * N + bx + bC);
        pb[it][1] = *(const float4*)(B + (size_t)(kr + 1) * N + bx + bC);
    }

    for (int kb = 0; kb < nk; kb++) {
        __syncthreads();
        // ---- convert + store staged tile ({hi,mid} uint2-interleaved) ----
#pragma unroll
        for (int it = 0; it < 4; it++) {
            const int am = aR + it * 32;
            uint32_t h01, m01, h23, m23;
            split_pack_bf16(pa[it].x, pa[it].y, h01, m01);
            split_pack_bf16(pa[it].z, pa[it].w, h23, m23);
            uint4 v; v.x = h01; v.y = m01; v.z = h23; v.w = m23;
            *(uint4*)&A2[am * A2ST + aKP] = v;
        }
#pragma unroll
        for (int it = 0; it < 2; it++) {
            const int kp = bKP + it * 8;
            uint32_t h0, m0, h1, m1, h2, m2, h3, m3;
            split_pack_bf16(pb[it][0].x, pb[it][1].x, h0, m0);
            split_pack_bf16(pb[it][0].y, pb[it][1].y, h1, m1);
            split_pack_bf16(pb[it][0].z, pb[it][1].z, h2, m2);
            split_pack_bf16(pb[it][0].w, pb[it][1].w, h3, m3);
            uint4 v0; v0.x = h0; v0.y = m0; v0.z = h1; v0.w = m1;
            uint4 v1; v1.x = h2; v1.y = m2; v1.z = h3; v1.w = m3;
            *(uint4*)&B2[kp * B2ST + bC]     = v0;
            *(uint4*)&B2[kp * B2ST + bC + 2] = v1;
        }
        __syncthreads();

        if (kb + 1 < nk) {
            const int k0 = (kb + 1) * GBK;
#pragma unroll
            for (int it = 0; it < 4; it++)
                pa[it] = *(const float4*)(A + (size_t)(by + aR + it * 32) * K + k0 + aC);
#pragma unroll
            for (int it = 0; it < 2; it++) {
                const int kr = k0 + 2 * (bKP + it * 8);
                pb[it][0] = *(const float4*)(B + (size_t)kr * N + bx + bC);
                pb[it][1] = *(const float4*)(B + (size_t)(kr + 1) * N + bx + bC);
            }
        }

        // ---- compute: 2 k-steps of 16 (kpairs kk..kk+7) ----
#pragma unroll
        for (int ks = 0; ks < 2; ks++) {
            const int kk = ks * 8;
            // A-frag: a0:(g, kp t)  a1:(g+8, kp t)  a2:(g, kp t+4)  a3:(g+8, kp t+4)
            uint2 af[4][4];   // [mt][a0..a3] = {hi, mid}
#pragma unroll
            for (int mt = 0; mt < 4; mt++) {
                const int r0 = wm * 64 + mt * 16 + gid;
                af[mt][0] = A2[r0 * A2ST + kk + tig];
                af[mt][1] = A2[(r0 + 8) * A2ST + kk + tig];
                af[mt][2] = A2[r0 * A2ST + kk + tig + 4];
                af[mt][3] = A2[(r0 + 8) * A2ST + kk + tig + 4];
            }
            // B-frag: b0:(kp t, n=g)  b1:(kp t+4, n=g)
            uint2 bf[4][2];
#pragma unroll
            for (int nt = 0; nt < 4; nt++) {
                const int c0 = wn * 32 + nt * 8 + gid;
                bf[nt][0] = B2[(kk + tig) * B2ST + c0];
                bf[nt][1] = B2[(kk + tig + 4) * B2ST + c0];
            }
#pragma unroll
            for (int mt = 0; mt < 4; mt++)
#pragma unroll
                for (int nt = 0; nt < 4; nt++) {
                    mma_bf16(acc[mt][nt], af[mt][0].x, af[mt][1].x, af[mt][2].x, af[mt][3].x,
                             bf[nt][0].x, bf[nt][1].x);
                    mma_bf16(acc[mt][nt], af[mt][0].x, af[mt][1].x, af[mt][2].x, af[mt][3].x,
                             bf[nt][0].y, bf[nt][1].y);
                    mma_bf16(acc[mt][nt], af[mt][0].y, af[mt][1].y, af[mt][2].y, af[mt][3].y,
                             bf[nt][0].x, bf[nt][1].x);
                }
        }
    }

    // epilogue: c0,c1 -> (row=g, col=2t..2t+1); c2,c3 -> (row=g+8, same cols)
#pragma unroll
    for (int mt = 0; mt < 4; mt++) {
        const int r0 = by + wm * 64 + mt * 16 + gid;
#pragma unroll
        for (int nt = 0; nt < 4; nt++) {
            const int c0 = bx + wn * 32 + nt * 8 + tig * 2;
            *(float2*)(C + (size_t)r0 * N + c0) =
                make_float2(acc[mt][nt][0], acc[mt][nt][1]);
            *(float2*)(C + (size_t)(r0 + 8) * N + c0) =
                make_float2(acc[mt][nt][2], acc[mt][nt][3]);
        }
    }
}

// ---------------- RoPE (in place, q and k in one launch) --------------------
__global__ void rope_kernel(float* __restrict__ q, float* __restrict__ k,
                            const int* __restrict__ start_pos)
{
    const long long qp = (long long)M_ * NH  * (HD / 2);
    const long long kp = (long long)M_ * NKV * (HD / 2);
    long long idx = (long long)blockIdx.x * blockDim.x + threadIdx.x;
    if (idx >= qp + kp) return;

    float* t;
    int nheads;
    if (idx < qp) { t = q; nheads = NH; }
    else          { t = k; nheads = NKV; idx -= qp; }

    const int ppr = nheads * (HD / 2);
    const int row = (int)(idx / ppr);
    const int pr  = (int)(idx % ppr);
    const int h   = pr / (HD / 2);
    const int i   = pr % (HD / 2);
    const int s   = row % S_;

    const float pos  = (float)(s + start_pos[0]);
    const float ex   = (float)(2 * i) * (1.0f / (float)HD);
    const float freq = powf(10000.0f, -ex);
    const float ang  = pos * freq;
    float sn, cs;
    sincosf(ang, &sn, &cs);

    float* p = t + (size_t)row * nheads * HD + (size_t)h * HD + 2 * i;
    const float tr = p[0];
    const float ti = p[1];
    p[0] = tr * cs - ti * sn;
    p[1] = tr * sn + ti * cs;
}

// =====================================================================
// Flash attention on tensor cores — bf16x3. EXACT round-12 version
// (measured 4780us total) — do not touch.
// =====================================================================
#define FQST 68
#define FKST 36
#define FVST 132
#define FPST 20
#define ATT3_SMEM ((64*FQST + 64*FKST + 16*FVST + 64*FPST) * 8 + 256 * 4)

__global__ __launch_bounds__(256) void attn_mma_kernel(
    const float* __restrict__ Q, const float* __restrict__ K,
    const float* __restrict__ V, float* __restrict__ O)
{
    extern __shared__ uint2 smu2[];
    uint2* Q2 = smu2;
    uint2* K2 = Q2 + 64 * FQST;
    uint2* V2 = K2 + 64 * FKST;
    uint2* P2 = V2 + 16 * FVST;
    float* pmax = (float*)(P2 + 64 * FPST);   // [2][64]
    float* psum = pmax + 128;                 // [2][64]

    const int qt = blockIdx.x, h = blockIdx.y, b = blockIdx.z;
    const int kvh = h >> 2;                   // N_REP = 4
    const int tid = threadIdx.x;
    const int wid = tid >> 5, lane = tid & 31;
    const int band = wid & 3;
    const int half = wid >> 2;
    const int gid = lane >> 2, tig = lane & 3;
    const int q0 = qt * 64;
    const float scale = 0.08838834764831845f;   // 1/sqrt(128)

    // ---- load Q tile, pre-scaled, bf16 hi/mid split over d-pairs ----
    {
        const int r  = tid >> 2;
        const int c0 = (tid & 3) * 4;
        const float* qrow = Q + (size_t)(b * S_ + q0 + r) * DIM + h * HD;
#pragma unroll
        for (int it = 0; it < 8; it++) {
            const int d = c0 + it * 16;
            float4 v = *(const float4*)(qrow + d);
            uint32_t h01, m01, h23, m23;
            split_pack_bf16(v.x * scale, v.y * scale, h01, m01);
            split_pack_bf16(v.z * scale, v.w * scale, h23, m23);
            uint2* dst = &Q2[r * FQST + (d >> 1)];
            dst[0] = make_uint2(h01, m01);
            dst[1] = make_uint2(h23, m23);
        }
    }

    const int r0 = band * 16 + gid;     // this lane's rows: r0, r0+8
    float m0 = -1e30f, m1 = -1e30f, l0 = 0.f, l1 = 0.f;
    float o[8][4];
#pragma unroll
    for (int nt = 0; nt < 8; nt++)
#pragma unroll
        for (int c = 0; c < 4; c++) o[nt][c] = 0.f;

    const int ktmax = 2 * qt + 1;
    for (int kt = 0; kt <= ktmax; kt++) {
        __syncthreads();   // K2/V2/P2 free (previous PV done), Q2 ready (kt=0)

        // ---- K tile: transposed [d-pair][key], bf16 hi/mid ----
        {
            const int key = tid & 31;
            const int dw  = (tid >> 5) * 4;
            const float* krow = K + (size_t)(b * S_ + kt * 32 + key) * (NKV * HD) + kvh * HD;
#pragma unroll
            for (int it = 0; it < 4; it++) {
                const int d = dw + it * 32;
                float4 v = *(const float4*)(krow + d);
                uint32_t h01, m01, h23, m23;
                split_pack_bf16(v.x, v.y, h01, m01);
                split_pack_bf16(v.z, v.w, h23, m23);
                K2[(d >> 1) * FKST + key]       = make_uint2(h01, m01);
                K2[((d >> 1) + 1) * FKST + key] = make_uint2(h23, m23);
            }
        }
        // ---- V tile: [key-pair][d], bf16 hi/mid (pairs over keys) ----
        {
            const int kp = tid >> 4;            // 0..15
            const int c0 = (tid & 15) * 8;      // 0..120
            const float* v0 = V + (size_t)(b * S_ + kt * 32 + 2 * kp) * (NKV * HD) + kvh * HD;
            const float* v1 = v0 + NKV * HD;
#pragma unroll
            for (int it = 0; it < 2; it++) {
                const int d = c0 + it * 4;
                float4 va = *(const float4*)(v0 + d);
                float4 vb = *(const float4*)(v1 + d);
                uint32_t h0, mm0, h1, mm1, h2, mm2, h3, mm3;
                split_pack_bf16(va.x, vb.x, h0, mm0);
                split_pack_bf16(va.y, vb.y, h1, mm1);
                split_pack_bf16(va.z, vb.z, h2, mm2);
                split_pack_bf16(va.w, vb.w, h3, mm3);
                uint2* dst = &V2[kp * FVST + d];
                dst[0] = make_uint2(h0, mm0);
                dst[1] = make_uint2(h1, mm1);
                dst[2] = make_uint2(h2, mm2);
                dst[3] = make_uint2(h3, mm3);
            }
        }
        __syncthreads();

        // ---- QK^T: 8 k-steps of 16 (8 d-pairs each) ----
        float s[2][4];
#pragma unroll
        for (int nt = 0; nt < 2; nt++)
#pragma unroll
            for (int c = 0; c < 4; c++) s[nt][c] = 0.f;

#pragma unroll
        for (int ksi = 0; ksi < 8; ksi++) {
            const int kk = ksi * 8;
            const uint2 A0 = Q2[r0 * FQST + kk + tig];
            const uint2 A1 = Q2[(r0 + 8) * FQST + kk + tig];
            const uint2 A2 = Q2[r0 * FQST + kk + tig + 4];
            const uint2 A3 = Q2[(r0 + 8) * FQST + kk + tig + 4];
#pragma unroll
            for (int nt = 0; nt < 2; nt++) {
                const int ck = half * 16 + nt * 8 + gid;
                const uint2 B0 = K2[(kk + tig) * FKST + ck];
                const uint2 B1 = K2[(kk + tig + 4) * FKST + ck];
                mma_bf16(s[nt], A0.x, A1.x, A2.x, A3.x, B0.x, B1.x);
                mma_bf16(s[nt], A0.x, A1.x, A2.x, A3.x, B0.y, B1.y);
                mma_bf16(s[nt], A0.y, A1.y, A2.y, A3.y, B0.x, B1.x);
            }
        }

        // ---- causal mask ----
        const int grow0 = q0 + r0, grow1 = grow0 + 8;
#pragma unroll
        for (int nt = 0; nt < 2; nt++) {
            const int col = kt * 32 + half * 16 + nt * 8 + tig * 2;
            if (col     > grow0) s[nt][0] = -1e30f;
            if (col + 1 > grow0) s[nt][1] = -1e30f;
            if (col     > grow1) s[nt][2] = -1e30f;
            if (col + 1 > grow1) s[nt][3] = -1e30f;
        }

        // ---- row max: quad reduce, then cross-half via smem ----
        float mx0 = fmaxf(fmaxf(s[0][0], s[0][1]), fmaxf(s[1][0], s[1][1]));
        float mx1 = fmaxf(fmaxf(s[0][2], s[0][3]), fmaxf(s[1][2], s[1][3]));
        mx0 = fmaxf(mx0, __shfl_xor_sync(0xffffffffu, mx0, 1));
        mx0 = fmaxf(mx0, __shfl_xor_sync(0xffffffffu, mx0, 2));
        mx1 = fmaxf(mx1, __shfl_xor_sync(0xffffffffu, mx1, 1));
        mx1 = fmaxf(mx1, __shfl_xor_sync(0xffffffffu, mx1, 2));
        if (tig == 0) {
            pmax[half * 64 + r0]     = mx0;
            pmax[half * 64 + r0 + 8] = mx1;
        }
        __syncthreads();
        const float M0 = fmaxf(pmax[r0],     pmax[64 + r0]);
        const float M1 = fmaxf(pmax[r0 + 8], pmax[64 + r0 + 8]);
        const float mn0 = fmaxf(m0, M0), mn1 = fmaxf(m1, M1);
        const float al0 = __expf(m0 - mn0), al1 = __expf(m1 - mn1);
        m0 = mn0; m1 = mn1;

        // ---- p = exp(s - m), partial sums, store P bf16 hi/mid ----
        float p[2][4];
#pragma unroll
        for (int nt = 0; nt < 2; nt++) {
            p[nt][0] = __expf(s[nt][0] - mn0);
            p[nt][1] = __expf(s[nt][1] - mn0);
            p[nt][2] = __expf(s[nt][2] - mn1);
            p[nt][3] = __expf(s[nt][3] - mn1);
        }
        float sm0 = p[0][0] + p[0][1] + p[1][0] + p[1][1];
        float sm1 = p[0][2] + p[0][3] + p[1][2] + p[1][3];
        sm0 += __shfl_xor_sync(0xffffffffu, sm0, 1);
        sm0 += __shfl_xor_sync(0xffffffffu, sm0, 2);
        sm1 += __shfl_xor_sync(0xffffffffu, sm1, 1);
        sm1 += __shfl_xor_sync(0xffffffffu, sm1, 2);
        if (tig == 0) {
            psum[half * 64 + r0]     = sm0;
            psum[half * 64 + r0 + 8] = sm1;
        }
#pragma unroll
        for (int nt = 0; nt < 2; nt++) {
            const int pkp = half * 8 + nt * 4 + tig;   // key-pair index
            uint32_t hh, mm;
            split_pack_bf16(p[nt][0], p[nt][1], hh, mm);
            P2[r0 * FPST + pkp] = make_uint2(hh, mm);
            split_pack_bf16(p[nt][2], p[nt][3], hh, mm);
            P2[(r0 + 8) * FPST + pkp] = make_uint2(hh, mm);
        }
        // rescale accumulators
#pragma unroll
        for (int nt = 0; nt < 8; nt++) {
            o[nt][0] *= al0; o[nt][1] *= al0;
            o[nt][2] *= al1; o[nt][3] *= al1;
        }
        __syncthreads();   // P2 + psum complete
        l0 = l0 * al0 + psum[r0]     + psum[64 + r0];
        l1 = l1 * al1 + psum[r0 + 8] + psum[64 + r0 + 8];

        // ---- O += P @ V: 2 k-steps of 16 (8 key-pairs each) ----
#pragma unroll
        for (int ksi = 0; ksi < 2; ksi++) {
            const int kk = ksi * 8;
            const uint2 A0 = P2[r0 * FPST + kk + tig];
            const uint2 A1 = P2[(r0 + 8) * FPST + kk + tig];
            const uint2 A2 = P2[r0 * FPST + kk + tig + 4];
            const uint2 A3 = P2[(r0 + 8) * FPST + kk + tig + 4];
#pragma unroll
            for (int nt = 0; nt < 8; nt++) {
                const int dc = half * 64 + nt * 8 + gid;
                const uint2 B0 = V2[(kk + tig) * FVST + dc];
                const uint2 B1 = V2[(kk + tig + 4) * FVST + dc];
                mma_bf16(o[nt], A0.x, A1.x, A2.x, A3.x, B0.x, B1.x);
                mma_bf16(o[nt], A0.x, A1.x, A2.x, A3.x, B0.y, B1.y);
                mma_bf16(o[nt], A0.y, A1.y, A2.y, A3.y, B0.x, B1.x);
            }
        }
    }

    // ---- epilogue: divide by l, write [b,s, h*128 + d] for the wo GEMM ----
    const float i0 = 1.f / l0, i1 = 1.f / l1;
    float* orow0 = O + (size_t)(b * S_ + q0 + r0) * DIM + h * HD;
    float* orow1 = orow0 + (size_t)8 * DIM;
#pragma unroll
    for (int nt = 0; nt < 8; nt++) {
        const int dc = half * 64 + nt * 8 + tig * 2;
        *(float2*)(orow0 + dc) = make_float2(o[nt][0] * i0, o[nt][1] * i0);
        *(float2*)(orow1 + dc) = make_float2(o[nt][2] * i1, o[nt][3] * i1);
    }
}

// ---------------- launch ----------------------------------------------------
extern "C" void kernel_launch(void* const* d_in, const int* in_sizes, int n_in,
                              void* d_out, int out_size)
{
    const float* x  = (const float*)d_in[0];
    const float* wq = (const float*)d_in[1];
    const float* wk = (const float*)d_in[2];
    const float* wv = (const float*)d_in[3];
    const float* wo = (const float*)d_in[4];
    // d_in[5] = mask (pure causal triu of -1e9; applied analytically)
    const int* start_pos = (const int*)d_in[6];
    float* out = (float*)d_out;

    float *q, *k, *v, *att;
    cudaGetSymbolAddress((void**)&q,   g_q);
    cudaGetSymbolAddress((void**)&k,   g_k);
    cudaGetSymbolAddress((void**)&v,   g_v);
    cudaGetSymbolAddress((void**)&att, g_att);

    cudaFuncSetAttribute(bf16_gemm_kernel,
                         cudaFuncAttributeMaxDynamicSharedMemorySize, GEMM_SMEM);
    cudaFuncSetAttribute(attn_mma_kernel,
                         cudaFuncAttributeMaxDynamicSharedMemorySize, ATT3_SMEM);

    // QKV projections (tensor-core bf16x3)
    bf16_gemm_kernel<<<dim3(DIM / GBN, M_ / GBM), 256, GEMM_SMEM>>>(
        x, wq, q, M_, DIM, DIM);
    bf16_gemm_kernel<<<dim3((NKV * HD) / GBN, M_ / GBM), 256, GEMM_SMEM>>>(
        x, wk, k, M_, NKV * HD, DIM);
    bf16_gemm_kernel<<<dim3((NKV * HD) / GBN, M_ / GBM), 256, GEMM_SMEM>>>(
        x, wv, v, M_, NKV * HD, DIM);

    // RoPE on q and k (single launch)
    {
        const long long pairs = (long long)M_ * (NH + NKV) * (HD / 2);
        rope_kernel<<<(unsigned)((pairs + 255) / 256), 256>>>(q, k, start_pos);
    }

    // attention (tensor-core bf16x3)
    attn_mma_kernel<<<dim3(S_ / 64, NH, B_), 256, ATT3_SMEM>>>(q, k, v, att);

    // output projection (tensor-core bf16x3)
    bf16_gemm_kernel<<<dim3(DIM / GBN, M_ / GBM), 256, GEMM_SMEM>>>(
        att, wo, out, M_, DIM, DIM);
}